// round 3
// baseline (speedup 1.0000x reference)
#include <cuda_runtime.h>
#include <cuda_bf16.h>
#include <cstdint>

// Problem dims
#define NXR 8192
#define NYR 8192
#define DK  512

// Tile config: CTA 128x256, 8 warps each 64x64, K-step 32
#define TM 128
#define TN 256
#define TK 32
#define KSTEPS (DK / TK)          // 16
#define STAGES 3

// SMEM: rows padded to 40 b16 (80B) for conflict-free ldmatrix.
#define ASTRIDE_B16 40
#define A_TILE_BYTES (TM * ASTRIDE_B16 * 2)         // 10240
#define B_TILE_BYTES (TN * ASTRIDE_B16 * 2)         // 20480
#define STAGE_BYTES  (A_TILE_BYTES + B_TILE_BYTES)  // 30720
#define SMEM_TOTAL   (STAGES * STAGE_BYTES)         // 92160

// bf16 scratch + row norms (device globals: no allocation allowed)
__device__ __nv_bfloat16 g_Xb[(size_t)NXR * DK];
__device__ __nv_bfloat16 g_Yb[(size_t)NYR * DK];
__device__ float g_x2[NXR];
__device__ float g_y2[NYR];

// ---------------- PTX helpers ----------------
__device__ __forceinline__ uint32_t smem_u32(const void* p) {
    uint32_t a;
    asm("{ .reg .u64 t; cvta.to.shared.u64 t, %1; cvt.u32.u64 %0, t; }" : "=r"(a) : "l"(p));
    return a;
}

#define CP_ASYNC16(saddr, gptr) \
    asm volatile("cp.async.cg.shared.global [%0], [%1], 16;" \
                 :: "r"(saddr), "l"(gptr) : "memory")

#define CP_COMMIT() asm volatile("cp.async.commit_group;" ::: "memory")
#define CP_WAIT(n)  asm volatile("cp.async.wait_group %0;" :: "n"(n) : "memory")

#define LDSM_X4(r, addr) \
    asm volatile("ldmatrix.sync.aligned.m8n8.x4.shared.b16 {%0,%1,%2,%3}, [%4];" \
                 : "=r"((r)[0]), "=r"((r)[1]), "=r"((r)[2]), "=r"((r)[3]) : "r"(addr))

#define MMA16816(d, a, b0, b1) \
    asm volatile("mma.sync.aligned.m16n8k16.row.col.f32.bf16.bf16.f32 " \
                 "{%0,%1,%2,%3}, {%4,%5,%6,%7}, {%8,%9}, {%0,%1,%2,%3};" \
                 : "+f"((d)[0]), "+f"((d)[1]), "+f"((d)[2]), "+f"((d)[3]) \
                 : "r"((a)[0]), "r"((a)[1]), "r"((a)[2]), "r"((a)[3]), \
                   "r"(b0), "r"(b1))

// ---------------- Prepass: f32 -> bf16 + row squared norms ----------------
__global__ void __launch_bounds__(128) rbf_prep_kernel(
    const float* __restrict__ x, const float* __restrict__ y) {
    __shared__ float red[4];
    int b = blockIdx.x;
    int t = threadIdx.x;
    const float* src;
    __nv_bfloat16* dst;
    float* nrm;
    int row;
    if (b < NXR) { row = b;       src = x + (size_t)row * DK; dst = g_Xb + (size_t)row * DK; nrm = g_x2; }
    else         { row = b - NXR; src = y + (size_t)row * DK; dst = g_Yb + (size_t)row * DK; nrm = g_y2; }

    float4 v = reinterpret_cast<const float4*>(src)[t];          // 128 threads x 4 = 512
    float s = v.x * v.x + v.y * v.y + v.z * v.z + v.w * v.w;
    __nv_bfloat162 h0 = __floats2bfloat162_rn(v.x, v.y);
    __nv_bfloat162 h1 = __floats2bfloat162_rn(v.z, v.w);
    reinterpret_cast<__nv_bfloat162*>(dst)[t * 2 + 0] = h0;
    reinterpret_cast<__nv_bfloat162*>(dst)[t * 2 + 1] = h1;

    #pragma unroll
    for (int o = 16; o; o >>= 1) s += __shfl_xor_sync(0xffffffffu, s, o);
    if ((t & 31) == 0) red[t >> 5] = s;
    __syncthreads();
    if (t == 0) nrm[row] = red[0] + red[1] + red[2] + red[3];
}

// ---------------- Tile loader (cp.async): 1536 x 16B over 256 threads ----------------
__device__ __forceinline__ void load_tile(
    uint32_t stage_base, const __nv_bfloat16* __restrict__ Arows,
    const __nv_bfloat16* __restrict__ Brows, int kstep, int tid) {
    // A: 128 rows x 4 segs = 512 requests (iters 0..1)
    #pragma unroll
    for (int h = 0; h < 2; h++) {
        int idx = tid + h * 256;
        int row = idx >> 2;
        int seg = idx & 3;
        uint32_t soff = (uint32_t)(row * (ASTRIDE_B16 * 2) + seg * 16);
        CP_ASYNC16(stage_base + soff,
                   Arows + (size_t)row * DK + kstep * TK + seg * 8);
    }
    // B: 256 rows x 4 segs = 1024 requests (iters 0..3)
    #pragma unroll
    for (int h = 0; h < 4; h++) {
        int idx = tid + h * 256;
        int row = idx >> 2;
        int seg = idx & 3;
        uint32_t soff = (uint32_t)(row * (ASTRIDE_B16 * 2) + seg * 16);
        CP_ASYNC16(stage_base + A_TILE_BYTES + soff,
                   Brows + (size_t)row * DK + kstep * TK + seg * 8);
    }
}

// ---------------- Main kernel: mma.sync GEMM + RBF epilogue ----------------
__global__ void __launch_bounds__(256, 1) rbf_gemm_kernel(
    float* __restrict__ out, const float* __restrict__ gamma_p) {
    extern __shared__ char smem[];
    const uint32_t sb = smem_u32(smem);
    const int tid = threadIdx.x;
    const int wid = tid >> 5;
    const int lid = tid & 31;
    const int wm = wid & 1;            // warp row: 64-row slab (2)
    const int wn = wid >> 1;           // warp col: 64-col slab (4)
    const int mbase = blockIdx.y * TM;
    const int nbase = blockIdx.x * TN;

    const __nv_bfloat16* Arows = g_Xb + (size_t)mbase * DK;
    const __nv_bfloat16* Brows = g_Yb + (size_t)nbase * DK;

    #pragma unroll
    for (int s = 0; s < STAGES - 1; s++) {
        load_tile(sb + s * STAGE_BYTES, Arows, Brows, s, tid);
        CP_COMMIT();
    }

    // acc[tm 0..3][nn 0..7][4] : warp 64x64 tile
    float acc[4][8][4];
    #pragma unroll
    for (int i = 0; i < 4; i++)
        #pragma unroll
        for (int j = 0; j < 8; j++)
            #pragma unroll
            for (int q = 0; q < 4; q++) acc[i][j][q] = 0.0f;

    const int lrow = lid & 15;
    const int lhalf = lid >> 4;

    for (int k = 0; k < KSTEPS; k++) {
        CP_WAIT(STAGES - 2);
        __syncthreads();
        const uint32_t st = sb + (k % STAGES) * STAGE_BYTES;
        const uint32_t abase = st + (uint32_t)((wm * 64 + lrow) * 80 + lhalf * 16);
        const uint32_t bbase = st + A_TILE_BYTES
                             + (uint32_t)((wn * 64 + lrow) * 80 + lhalf * 16);

        // ---- kk = 0 fragments ----
        uint32_t a0[4][4], b0[4][4];
        #pragma unroll
        for (int tm = 0; tm < 4; tm++) LDSM_X4(a0[tm], abase + tm * (16 * 80));
        #pragma unroll
        for (int p = 0; p < 4; p++)    LDSM_X4(b0[p],  bbase + p * (16 * 80));

        // Issue next-stage loads now so they overlap the MMA burst below.
        if (k + STAGES - 1 < KSTEPS) {
            load_tile(sb + ((k + STAGES - 1) % STAGES) * STAGE_BYTES,
                      Arows, Brows, k + STAGES - 1, tid);
        }
        CP_COMMIT();

        #pragma unroll
        for (int tm = 0; tm < 4; tm++)
            #pragma unroll
            for (int p = 0; p < 4; p++) {
                MMA16816(acc[tm][2 * p + 0], a0[tm], b0[p][0], b0[p][2]);
                MMA16816(acc[tm][2 * p + 1], a0[tm], b0[p][1], b0[p][3]);
            }

        // ---- kk = 1 fragments ----
        uint32_t a1[4][4], b1[4][4];
        #pragma unroll
        for (int tm = 0; tm < 4; tm++) LDSM_X4(a1[tm], abase + 32 + tm * (16 * 80));
        #pragma unroll
        for (int p = 0; p < 4; p++)    LDSM_X4(b1[p],  bbase + 32 + p * (16 * 80));

        #pragma unroll
        for (int tm = 0; tm < 4; tm++)
            #pragma unroll
            for (int p = 0; p < 4; p++) {
                MMA16816(acc[tm][2 * p + 0], a1[tm], b1[p][0], b1[p][2]);
                MMA16816(acc[tm][2 * p + 1], a1[tm], b1[p][1], b1[p][3]);
            }
    }

    // ---------------- Epilogue ----------------
    const float gam = __ldg(gamma_p);
    #pragma unroll
    for (int tm = 0; tm < 4; tm++) {
        const int m0 = mbase + wm * 64 + tm * 16 + (lid >> 2);
        const float x2a = g_x2[m0];
        const float x2b = g_x2[m0 + 8];
        #pragma unroll
        for (int nn = 0; nn < 8; nn++) {
            const int n0 = nbase + wn * 64 + nn * 8 + (lid & 3) * 2;
            const float y2a = g_y2[n0];
            const float y2b = g_y2[n0 + 1];
            const float* c = acc[tm][nn];
            float2 v0, v1;
            v0.x = __expf(-gam * fmaxf(x2a + y2a - 2.0f * c[0], 0.0f));
            v0.y = __expf(-gam * fmaxf(x2a + y2b - 2.0f * c[1], 0.0f));
            v1.x = __expf(-gam * fmaxf(x2b + y2a - 2.0f * c[2], 0.0f));
            v1.y = __expf(-gam * fmaxf(x2b + y2b - 2.0f * c[3], 0.0f));
            *reinterpret_cast<float2*>(out + (size_t)m0 * NYR + n0) = v0;
            *reinterpret_cast<float2*>(out + (size_t)(m0 + 8) * NYR + n0) = v1;
        }
    }
}

extern "C" void kernel_launch(void* const* d_in, const int* in_sizes, int n_in,
                              void* d_out, int out_size) {
    const float* x = (const float*)d_in[0];
    const float* y = (const float*)d_in[1];
    const float* gamma = (const float*)d_in[2];
    float* out = (float*)d_out;

    rbf_prep_kernel<<<NXR + NYR, 128>>>(x, y);

    cudaFuncSetAttribute(rbf_gemm_kernel,
                         cudaFuncAttributeMaxDynamicSharedMemorySize, SMEM_TOTAL);
    dim3 grid(NYR / TN, NXR / TM);
    rbf_gemm_kernel<<<grid, 256, SMEM_TOTAL>>>(out, gamma);
}

// round 4
// speedup vs baseline: 1.2199x; 1.2199x over previous
#include <cuda_runtime.h>
#include <cuda_bf16.h>
#include <cstdint>

// Problem dims
#define NXR 8192
#define NYR 8192
#define DK  512

// Tile config: CTA 128x128, 8 warps each 32x64, K-step 32, 4 stages, 2 CTAs/SM
#define TM 128
#define TN 128
#define TK 32
#define KSTEPS (DK / TK)          // 16
#define STAGES 4

// SMEM: rows padded to 40 b16 (80B) for conflict-free ldmatrix.
#define ASTRIDE_B16 40
#define A_TILE_BYTES (TM * ASTRIDE_B16 * 2)         // 10240
#define B_TILE_BYTES (TN * ASTRIDE_B16 * 2)         // 10240
#define STAGE_BYTES  (A_TILE_BYTES + B_TILE_BYTES)  // 20480
#define SMEM_TOTAL   (STAGES * STAGE_BYTES)         // 81920

// bf16 scratch + row norms (device globals: no allocation allowed)
__device__ __nv_bfloat16 g_Xb[(size_t)NXR * DK];
__device__ __nv_bfloat16 g_Yb[(size_t)NYR * DK];
__device__ float g_x2[NXR];
__device__ float g_y2[NYR];

// ---------------- PTX helpers ----------------
__device__ __forceinline__ uint32_t smem_u32(const void* p) {
    uint32_t a;
    asm("{ .reg .u64 t; cvta.to.shared.u64 t, %1; cvt.u32.u64 %0, t; }" : "=r"(a) : "l"(p));
    return a;
}

#define CP_ASYNC16(saddr, gptr) \
    asm volatile("cp.async.cg.shared.global [%0], [%1], 16;" \
                 :: "r"(saddr), "l"(gptr) : "memory")

#define CP_COMMIT() asm volatile("cp.async.commit_group;" ::: "memory")
#define CP_WAIT(n)  asm volatile("cp.async.wait_group %0;" :: "n"(n) : "memory")

#define LDSM_X4(r, addr) \
    asm volatile("ldmatrix.sync.aligned.m8n8.x4.shared.b16 {%0,%1,%2,%3}, [%4];" \
                 : "=r"((r)[0]), "=r"((r)[1]), "=r"((r)[2]), "=r"((r)[3]) : "r"(addr))

#define MMA16816(d, a, b0, b1) \
    asm volatile("mma.sync.aligned.m16n8k16.row.col.f32.bf16.bf16.f32 " \
                 "{%0,%1,%2,%3}, {%4,%5,%6,%7}, {%8,%9}, {%0,%1,%2,%3};" \
                 : "+f"((d)[0]), "+f"((d)[1]), "+f"((d)[2]), "+f"((d)[3]) \
                 : "r"((a)[0]), "r"((a)[1]), "r"((a)[2]), "r"((a)[3]), \
                   "r"(b0), "r"(b1))

// ---------------- Prepass: f32 -> bf16 + row squared norms ----------------
__global__ void __launch_bounds__(128) rbf_prep_kernel(
    const float* __restrict__ x, const float* __restrict__ y) {
    __shared__ float red[4];
    int b = blockIdx.x;
    int t = threadIdx.x;
    const float* src;
    __nv_bfloat16* dst;
    float* nrm;
    int row;
    if (b < NXR) { row = b;       src = x + (size_t)row * DK; dst = g_Xb + (size_t)row * DK; nrm = g_x2; }
    else         { row = b - NXR; src = y + (size_t)row * DK; dst = g_Yb + (size_t)row * DK; nrm = g_y2; }

    float4 v = reinterpret_cast<const float4*>(src)[t];          // 128 threads x 4 = 512
    float s = v.x * v.x + v.y * v.y + v.z * v.z + v.w * v.w;
    __nv_bfloat162 h0 = __floats2bfloat162_rn(v.x, v.y);
    __nv_bfloat162 h1 = __floats2bfloat162_rn(v.z, v.w);
    reinterpret_cast<__nv_bfloat162*>(dst)[t * 2 + 0] = h0;
    reinterpret_cast<__nv_bfloat162*>(dst)[t * 2 + 1] = h1;

    #pragma unroll
    for (int o = 16; o; o >>= 1) s += __shfl_xor_sync(0xffffffffu, s, o);
    if ((t & 31) == 0) red[t >> 5] = s;
    __syncthreads();
    if (t == 0) nrm[row] = red[0] + red[1] + red[2] + red[3];
}

// ---------------- Main kernel: mma.sync GEMM + RBF epilogue ----------------
__global__ void __launch_bounds__(256, 2) rbf_gemm_kernel(
    float* __restrict__ out, const float* __restrict__ gamma_p) {
    extern __shared__ char smem[];
    const uint32_t sb = smem_u32(smem);
    const int tid = threadIdx.x;
    const int wid = tid >> 5;
    const int lid = tid & 31;
    const int wm = wid & 3;            // warp row: 32-row slab (4)
    const int wn = wid >> 2;           // warp col: 64-col slab (2)
    const int mbase = blockIdx.y * TM;
    const int nbase = blockIdx.x * TN;

    // ---- per-thread load assignment: 4 x 16B chunks per stage ----
    // A: idx = tid, tid+256 -> row = idx>>1, seg = idx&1 covers 128 rows x 2 segs? No:
    // 128 rows x 4 segs(16B) = 512 chunks; thread handles idx=tid and tid+256.
    const int arow0 = tid >> 2,            aseg0 = tid & 3;
    const int arow1 = (tid + 256) >> 2,    aseg1 = (tid + 256) & 3;
    const __nv_bfloat16* aptr0 = g_Xb + (size_t)(mbase + arow0) * DK + aseg0 * 8;
    const __nv_bfloat16* aptr1 = g_Xb + (size_t)(mbase + arow1) * DK + aseg1 * 8;
    const __nv_bfloat16* bptr0 = g_Yb + (size_t)(nbase + arow0) * DK + aseg0 * 8;
    const __nv_bfloat16* bptr1 = g_Yb + (size_t)(nbase + arow1) * DK + aseg1 * 8;
    const uint32_t soA0 = (uint32_t)(arow0 * (ASTRIDE_B16 * 2) + aseg0 * 16);
    const uint32_t soA1 = (uint32_t)(arow1 * (ASTRIDE_B16 * 2) + aseg1 * 16);

    int ldk = 0;  // next k-step to load
    #pragma unroll
    for (int s = 0; s < STAGES - 1; s++) {
        const uint32_t st = sb + s * STAGE_BYTES;
        CP_ASYNC16(st + soA0, aptr0 + ldk * TK);
        CP_ASYNC16(st + soA1, aptr1 + ldk * TK);
        CP_ASYNC16(st + A_TILE_BYTES + soA0, bptr0 + ldk * TK);
        CP_ASYNC16(st + A_TILE_BYTES + soA1, bptr1 + ldk * TK);
        CP_COMMIT();
        ldk++;
    }

    // acc[tm 0..1][nn 0..7][4] : warp 32x64 tile
    float acc[2][8][4];
    #pragma unroll
    for (int i = 0; i < 2; i++)
        #pragma unroll
        for (int j = 0; j < 8; j++)
            #pragma unroll
            for (int q = 0; q < 4; q++) acc[i][j][q] = 0.0f;

    const int lrow = lid & 15;
    const int lhalf = lid >> 4;
    const uint32_t aoff = (uint32_t)((wm * 32 + lrow) * 80 + lhalf * 16);
    const uint32_t boff = (uint32_t)(A_TILE_BYTES + (wn * 64 + lrow) * 80 + lhalf * 16);

    for (int k = 0; k < KSTEPS; k++) {
        CP_WAIT(STAGES - 2);
        __syncthreads();
        const uint32_t st = sb + (k & (STAGES - 1)) * STAGE_BYTES;

        // Issue next-stage loads first; they drain under the MMA burst.
        if (ldk < KSTEPS) {
            const uint32_t ls = sb + (ldk & (STAGES - 1)) * STAGE_BYTES;
            CP_ASYNC16(ls + soA0, aptr0 + ldk * TK);
            CP_ASYNC16(ls + soA1, aptr1 + ldk * TK);
            CP_ASYNC16(ls + A_TILE_BYTES + soA0, bptr0 + ldk * TK);
            CP_ASYNC16(ls + A_TILE_BYTES + soA1, bptr1 + ldk * TK);
            ldk++;
        }
        CP_COMMIT();

        #pragma unroll
        for (int kk = 0; kk < 2; kk++) {
            uint32_t a[2][4], b[4][4];
            #pragma unroll
            for (int tm = 0; tm < 2; tm++)
                LDSM_X4(a[tm], st + aoff + kk * 32 + tm * (16 * 80));
            #pragma unroll
            for (int p = 0; p < 4; p++)
                LDSM_X4(b[p], st + boff + kk * 32 + p * (16 * 80));

            #pragma unroll
            for (int tm = 0; tm < 2; tm++)
                #pragma unroll
                for (int p = 0; p < 4; p++) {
                    MMA16816(acc[tm][2 * p + 0], a[tm], b[p][0], b[p][2]);
                    MMA16816(acc[tm][2 * p + 1], a[tm], b[p][1], b[p][3]);
                }
        }
    }

    // ---------------- Epilogue ----------------
    const float gam = __ldg(gamma_p);
    #pragma unroll
    for (int tm = 0; tm < 2; tm++) {
        const int m0 = mbase + wm * 32 + tm * 16 + (lid >> 2);
        const float x2a = g_x2[m0];
        const float x2b = g_x2[m0 + 8];
        #pragma unroll
        for (int nn = 0; nn < 8; nn++) {
            const int n0 = nbase + wn * 64 + nn * 8 + (lid & 3) * 2;
            const float y2a = g_y2[n0];
            const float y2b = g_y2[n0 + 1];
            const float* c = acc[tm][nn];
            float2 v0, v1;
            v0.x = __expf(-gam * fmaxf(x2a + y2a - 2.0f * c[0], 0.0f));
            v0.y = __expf(-gam * fmaxf(x2a + y2b - 2.0f * c[1], 0.0f));
            v1.x = __expf(-gam * fmaxf(x2b + y2a - 2.0f * c[2], 0.0f));
            v1.y = __expf(-gam * fmaxf(x2b + y2b - 2.0f * c[3], 0.0f));
            *reinterpret_cast<float2*>(out + (size_t)m0 * NYR + n0) = v0;
            *reinterpret_cast<float2*>(out + (size_t)(m0 + 8) * NYR + n0) = v1;
        }
    }
}

extern "C" void kernel_launch(void* const* d_in, const int* in_sizes, int n_in,
                              void* d_out, int out_size) {
    const float* x = (const float*)d_in[0];
    const float* y = (const float*)d_in[1];
    const float* gamma = (const float*)d_in[2];
    float* out = (float*)d_out;

    rbf_prep_kernel<<<NXR + NYR, 128>>>(x, y);

    cudaFuncSetAttribute(rbf_gemm_kernel,
                         cudaFuncAttributeMaxDynamicSharedMemorySize, SMEM_TOTAL);
    dim3 grid(NYR / TN, NXR / TM);
    rbf_gemm_kernel<<<grid, 256, SMEM_TOTAL>>>(out, gamma);
}